// round 6
// baseline (speedup 1.0000x reference)
#include <cuda_runtime.h>
#include <cuda_bf16.h>
#include <math.h>

#define NN_MAX 50000
#define EE_MAX 600000
#define DD 128
#define HH 4
#define CC 32
#define NEG_SLOPE 0.2f
#define LN_EPS 1e-5f
#define NB_MAX 256

// ---------------- device scratch ----------------
static __device__ float g_h[NN_MAX * DD];
static __device__ float g_asrc[NN_MAX * HH];
static __device__ float g_adst[NN_MAX * HH];
static __device__ int   g_deg[NN_MAX];
static __device__ int   g_rowoff[NN_MAX];
static __device__ int   g_cursor[NN_MAX];
static __device__ int   g_srclist[EE_MAX];
static __device__ int   g_bsum[NB_MAX];
static __device__ int   g_is64;

__device__ __forceinline__ float lrelu(float v) {
    return (v > 0.f) ? v : v * NEG_SLOPE;
}

// ---------------- tf32 helpers ----------------
__device__ __forceinline__ unsigned f2tf32(float v) {
    unsigned r;
    asm("cvt.rna.tf32.f32 %0, %1;" : "=r"(r) : "f"(v));
    return r;
}
__device__ __forceinline__ void mma_tf32(float4& d,
    unsigned a0, unsigned a1, unsigned a2, unsigned a3,
    unsigned b0, unsigned b1)
{
    asm volatile(
        "mma.sync.aligned.m16n8k8.row.col.f32.tf32.tf32.f32 "
        "{%0,%1,%2,%3}, {%4,%5,%6,%7}, {%8,%9}, {%0,%1,%2,%3};"
        : "+f"(d.x), "+f"(d.y), "+f"(d.z), "+f"(d.w)
        : "r"(a0), "r"(a1), "r"(a2), "r"(a3), "r"(b0), "r"(b1));
}

// ---------------- Kernel 0: zero degrees + detect dtype ----------------
__global__ void detect_zero_kernel(const int* __restrict__ ei32, int E, int n)
{
    int i = blockIdx.x * 256 + threadIdx.x;
    if (i < n) g_deg[i] = 0;
    if (blockIdx.x == 0) {
        int checks = 2 * E; if (checks > 4096) checks = 4096;
        int nz = 0;
        for (int j = threadIdx.x; j < checks; j += 256)
            if (ei32[2 * j + 1] != 0) nz = 1;
        #pragma unroll
        for (int o = 16; o >= 1; o >>= 1)
            nz |= __shfl_xor_sync(0xffffffffu, nz, o);
        __shared__ int s_nz[8];
        if ((threadIdx.x & 31) == 0) s_nz[threadIdx.x >> 5] = nz;
        __syncthreads();
        if (threadIdx.x == 0) {
            int a = 0;
            for (int w = 0; w < 8; w++) a |= s_nz[w];
            g_is64 = (a == 0) ? 1 : 0;
        }
    }
}

__device__ __forceinline__ int edge_src(const void* ei, int E, int e) {
    if (g_is64) return (int)((const long long*)ei)[e];
    return ((const int*)ei)[e];
}
__device__ __forceinline__ int edge_dst(const void* ei, int E, int e) {
    if (g_is64) return (int)((const long long*)ei)[E + e];
    return ((const int*)ei)[E + e];
}

// ---------------- Kernel 1: h = x @ W via TF32 tensor cores -------------
// Block: 256 threads (8 warps). Block tile: 128 rows x 128 cols, K=128.
// Warp w owns rows [w*16, w*16+16). 3-pass tf32 split => ~fp32 precision.
// smem: xs[128][132] floats (x tile), wp[128][132] float2 (W hi/lo tf32).
#define XS_STRIDE 132
#define WP_STRIDE 132

__global__ __launch_bounds__(256, 1)
void gemm_kernel(const float* __restrict__ x, const float* __restrict__ W,
                 const float* __restrict__ att_src, const float* __restrict__ att_dst,
                 int n)
{
    extern __shared__ float smem[];
    float*  xs = smem;                                // 128*132 floats
    float2* wp = (float2*)(smem + 128 * XS_STRIDE);   // 128*132 float2

    int tid = threadIdx.x;
    int rowbase = blockIdx.x * 128;

    // Stage W as tf32 hi/lo pairs
    for (int idx = tid; idx < 128 * 128; idx += 256) {
        int k = idx >> 7, c = idx & 127;
        float v = W[idx];
        unsigned hi = f2tf32(v);
        float hif = __uint_as_float(hi);
        unsigned lo = f2tf32(v - hif);
        wp[k * WP_STRIDE + c] = make_float2(hif, __uint_as_float(lo));
    }

    // Stage x tile (zero-padded beyond n)
    const float4* x4in = (const float4*)x;
    for (int idx = tid; idx < 128 * 32; idx += 256) {
        int r = idx >> 5, c4 = idx & 31;
        int grow = rowbase + r;
        float4 v = make_float4(0.f, 0.f, 0.f, 0.f);
        if (grow < n) v = x4in[grow * 32 + c4];
        ((float4*)(xs + r * XS_STRIDE))[c4] = v;
    }
    __syncthreads();

    int w    = tid >> 5;
    int lane = tid & 31;
    int g = lane >> 2;          // 0..7
    int t = lane & 3;           // 0..3
    int r0 = w * 16 + g;        // local row of c0/c1
    int r1 = r0 + 8;            // local row of c2/c3

    float4 acc[16];
    #pragma unroll
    for (int nt = 0; nt < 16; nt++) acc[nt] = make_float4(0.f, 0.f, 0.f, 0.f);

    #pragma unroll
    for (int ks = 0; ks < 16; ks++) {
        int kb = ks * 8;
        float av0 = xs[r0 * XS_STRIDE + kb + t];
        float av1 = xs[r1 * XS_STRIDE + kb + t];
        float av2 = xs[r0 * XS_STRIDE + kb + t + 4];
        float av3 = xs[r1 * XS_STRIDE + kb + t + 4];
        unsigned a0h = f2tf32(av0), a1h = f2tf32(av1);
        unsigned a2h = f2tf32(av2), a3h = f2tf32(av3);
        unsigned a0l = f2tf32(av0 - __uint_as_float(a0h));
        unsigned a1l = f2tf32(av1 - __uint_as_float(a1h));
        unsigned a2l = f2tf32(av2 - __uint_as_float(a2h));
        unsigned a3l = f2tf32(av3 - __uint_as_float(a3h));

        const float2* wr0 = wp + (kb + t) * WP_STRIDE;
        const float2* wr1 = wp + (kb + t + 4) * WP_STRIDE;
        #pragma unroll
        for (int nt = 0; nt < 16; nt++) {
            float2 b0 = wr0[nt * 8 + g];
            float2 b1 = wr1[nt * 8 + g];
            unsigned b0h = __float_as_uint(b0.x), b1h = __float_as_uint(b1.x);
            unsigned b0l = __float_as_uint(b0.y), b1l = __float_as_uint(b1.y);
            mma_tf32(acc[nt], a0h, a1h, a2h, a3h, b0h, b1h);   // hi*hi
            mma_tf32(acc[nt], a0l, a1l, a2l, a3l, b0h, b1h);   // lo*hi
            mma_tf32(acc[nt], a0h, a1h, a2h, a3h, b0l, b1l);   // hi*lo
        }
    }

    // Epilogue: store h (float2, quad-contiguous 32B) + attention logits.
    int grow0 = rowbase + r0;
    int grow1 = rowbase + r1;
    float as0[4] = {0.f, 0.f, 0.f, 0.f}, ad0[4] = {0.f, 0.f, 0.f, 0.f};
    float as1[4] = {0.f, 0.f, 0.f, 0.f}, ad1[4] = {0.f, 0.f, 0.f, 0.f};

    #pragma unroll
    for (int nt = 0; nt < 16; nt++) {
        int c = nt * 8 + 2 * t;
        int head = nt >> 2;
        float sA = __ldg(att_src + c), sB = __ldg(att_src + c + 1);
        float dA = __ldg(att_dst + c), dB = __ldg(att_dst + c + 1);
        as0[head] += acc[nt].x * sA + acc[nt].y * sB;
        ad0[head] += acc[nt].x * dA + acc[nt].y * dB;
        as1[head] += acc[nt].z * sA + acc[nt].w * sB;
        ad1[head] += acc[nt].z * dA + acc[nt].w * dB;
        if (grow0 < n)
            *(float2*)(g_h + grow0 * 128 + c) = make_float2(acc[nt].x, acc[nt].y);
        if (grow1 < n)
            *(float2*)(g_h + grow1 * 128 + c) = make_float2(acc[nt].z, acc[nt].w);
    }
    // reduce across the 4 threads of the quad (same row)
    #pragma unroll
    for (int h = 0; h < 4; h++) {
        #pragma unroll
        for (int o = 1; o <= 2; o <<= 1) {
            as0[h] += __shfl_xor_sync(0xffffffffu, as0[h], o);
            ad0[h] += __shfl_xor_sync(0xffffffffu, ad0[h], o);
            as1[h] += __shfl_xor_sync(0xffffffffu, as1[h], o);
            ad1[h] += __shfl_xor_sync(0xffffffffu, ad1[h], o);
        }
    }
    if (t == 0) {
        if (grow0 < n) {
            ((float4*)g_asrc)[grow0] = make_float4(as0[0], as0[1], as0[2], as0[3]);
            ((float4*)g_adst)[grow0] = make_float4(ad0[0], ad0[1], ad0[2], ad0[3]);
        }
        if (grow1 < n) {
            ((float4*)g_asrc)[grow1] = make_float4(as1[0], as1[1], as1[2], as1[3]);
            ((float4*)g_adst)[grow1] = make_float4(ad1[0], ad1[1], ad1[2], ad1[3]);
        }
    }
}

// ---------------- Kernel 2: histogram of dst ----------------
__global__ void hist_kernel(const void* __restrict__ ei, int E)
{
    int e = blockIdx.x * 256 + threadIdx.x;
    if (e < E) {
        int d = edge_dst(ei, E, e);
        atomicAdd(&g_deg[d], 1);
    }
}

// ---------------- Kernel 3a: per-block local exclusive scan -------------
__global__ __launch_bounds__(256)
void scan_local_kernel(int n)
{
    int i = blockIdx.x * 256 + threadIdx.x;
    int lane = threadIdx.x & 31;
    int wid  = threadIdx.x >> 5;
    int v = (i < n) ? g_deg[i] : 0;

    int inc = v;
    #pragma unroll
    for (int o = 1; o < 32; o <<= 1) {
        int t = __shfl_up_sync(0xffffffffu, inc, o);
        if (lane >= o) inc += t;
    }
    __shared__ int wsum[8];
    if (lane == 31) wsum[wid] = inc;
    __syncthreads();
    if (wid == 0) {
        int ws = (lane < 8) ? wsum[lane] : 0;
        #pragma unroll
        for (int o = 1; o < 8; o <<= 1) {
            int t = __shfl_up_sync(0xffffffffu, ws, o);
            if (lane >= o) ws += t;
        }
        if (lane < 8) wsum[lane] = ws;
    }
    __syncthreads();
    int warpbase = (wid == 0) ? 0 : wsum[wid - 1];
    int excl = warpbase + inc - v;
    if (i < n) g_rowoff[i] = excl;
    if (threadIdx.x == 255) g_bsum[blockIdx.x] = warpbase + inc;
}

// ---------------- Kernel 3b: fixup ----------------
__global__ __launch_bounds__(256)
void scan_fixup_kernel(int n, int nb)
{
    __shared__ int s_base;
    if (threadIdx.x < 32) {
        int b = 0;
        for (int j = threadIdx.x; j < blockIdx.x; j += 32) b += g_bsum[j];
        #pragma unroll
        for (int o = 16; o >= 1; o >>= 1)
            b += __shfl_xor_sync(0xffffffffu, b, o);
        if (threadIdx.x == 0) s_base = b;
    }
    __syncthreads();
    int i = blockIdx.x * 256 + threadIdx.x;
    if (i < n) {
        int r = g_rowoff[i] + s_base;
        g_rowoff[i] = r;
        g_cursor[i] = r;
    }
}

// ---------------- Kernel 4: scatter edges into CSR ----------------
__global__ void scatter_kernel(const void* __restrict__ ei, int E)
{
    int e = blockIdx.x * 256 + threadIdx.x;
    if (e < E) {
        int s = edge_src(ei, E, e);
        int d = edge_dst(ei, E, e);
        int pos = atomicAdd(&g_cursor[d], 1);
        g_srclist[pos] = s;
    }
}

// ---------------- Kernel 5: fused softmax-agg + GELU + LN + residual ----
// (R3 version — proven fastest)
__global__ __launch_bounds__(256)
void agg_ln_kernel(const float* __restrict__ x,
                   const float* __restrict__ bias,
                   const float* __restrict__ gamma,
                   const float* __restrict__ beta,
                   float* __restrict__ out, int n)
{
    int node = blockIdx.x * 8 + (threadIdx.x >> 5);
    if (node >= n) return;
    int lane = threadIdx.x & 31;
    int hd8 = lane >> 3;
    int hd4 = lane & 3;
    int esub = lane >> 2;

    int beg = g_rowoff[node];
    int cnt = g_deg[node];

    float aself = g_asrc[node * HH + hd4];
    float adst4 = g_adst[node * HH + hd4];

    // Phase A: per-head max of a_src over {self} U neighbors
    float mx = aself;
    for (int k0 = 0; k0 < cnt; k0 += 8) {
        int k = k0 + esub;
        float v = -1e30f;
        if (k < cnt) {
            int s = g_srclist[beg + k];
            v = g_asrc[s * HH + hd4];
        }
        mx = fmaxf(mx, v);
    }
    mx = fmaxf(mx, __shfl_xor_sync(0xffffffffu, mx, 4));
    mx = fmaxf(mx, __shfl_xor_sync(0xffffffffu, mx, 8));
    mx = fmaxf(mx, __shfl_xor_sync(0xffffffffu, mx, 16));

    float mxh    = __shfl_sync(0xffffffffu, mx, hd8);
    float adst   = __shfl_sync(0xffffffffu, adst4, hd8);
    float aselfh = __shfl_sync(0xffffffffu, aself, hd8);
    float M = lrelu(mxh + adst);

    // Phase B: weighted aggregation
    const float4* h4 = (const float4*)g_h;
    float p0 = __expf(lrelu(aselfh + adst) - M);
    float4 hv = h4[node * 32 + lane];
    float4 accA = make_float4(p0 * hv.x, p0 * hv.y, p0 * hv.z, p0 * hv.w);
    float4 accB = make_float4(0.f, 0.f, 0.f, 0.f);
    float dA = p0, dB = 0.f;

    int k = 0;
    for (; k + 2 <= cnt; k += 2) {
        int sa = g_srclist[beg + k];
        int sb = g_srclist[beg + k + 1];
        float ea = g_asrc[sa * HH + hd8];
        float eb = g_asrc[sb * HH + hd8];
        float4 ha = h4[sa * 32 + lane];
        float4 hb = h4[sb * 32 + lane];
        float pa = __expf(lrelu(ea + adst) - M);
        float pb = __expf(lrelu(eb + adst) - M);
        dA += pa; dB += pb;
        accA.x = fmaf(pa, ha.x, accA.x); accA.y = fmaf(pa, ha.y, accA.y);
        accA.z = fmaf(pa, ha.z, accA.z); accA.w = fmaf(pa, ha.w, accA.w);
        accB.x = fmaf(pb, hb.x, accB.x); accB.y = fmaf(pb, hb.y, accB.y);
        accB.z = fmaf(pb, hb.z, accB.z); accB.w = fmaf(pb, hb.w, accB.w);
    }
    if (k < cnt) {
        int sa = g_srclist[beg + k];
        float ea = g_asrc[sa * HH + hd8];
        float4 ha = h4[sa * 32 + lane];
        float pa = __expf(lrelu(ea + adst) - M);
        dA += pa;
        accA.x = fmaf(pa, ha.x, accA.x); accA.y = fmaf(pa, ha.y, accA.y);
        accA.z = fmaf(pa, ha.z, accA.z); accA.w = fmaf(pa, ha.w, accA.w);
    }

    float denom = dA + dB;
    float inv = 1.0f / denom;
    float4 bi = ((const float4*)bias)[lane];
    float4 o = make_float4(fmaf(accA.x + accB.x, inv, bi.x),
                           fmaf(accA.y + accB.y, inv, bi.y),
                           fmaf(accA.z + accB.z, inv, bi.z),
                           fmaf(accA.w + accB.w, inv, bi.w));

    const float RS2 = 0.70710678118654752f;
    float4 f;
    f.x = 0.5f * o.x * (1.0f + erff(o.x * RS2));
    f.y = 0.5f * o.y * (1.0f + erff(o.y * RS2));
    f.z = 0.5f * o.z * (1.0f + erff(o.z * RS2));
    f.w = 0.5f * o.w * (1.0f + erff(o.w * RS2));

    float s1 = f.x + f.y + f.z + f.w;
    float s2 = f.x * f.x + f.y * f.y + f.z * f.z + f.w * f.w;
    #pragma unroll
    for (int off = 16; off >= 1; off >>= 1) {
        s1 += __shfl_xor_sync(0xffffffffu, s1, off);
        s2 += __shfl_xor_sync(0xffffffffu, s2, off);
    }
    float mu  = s1 * (1.0f / 128.0f);
    float var = s2 * (1.0f / 128.0f) - mu * mu;
    float r = rsqrtf(var + LN_EPS);

    float4 gm = ((const float4*)gamma)[lane];
    float4 bt = ((const float4*)beta)[lane];
    float4 xv = ((const float4*)x)[node * 32 + lane];
    float4 res;
    res.x = (f.x - mu) * r * gm.x + bt.x + xv.x;
    res.y = (f.y - mu) * r * gm.y + bt.y + xv.y;
    res.z = (f.z - mu) * r * gm.z + bt.z + xv.z;
    res.w = (f.w - mu) * r * gm.w + bt.w + xv.w;
    ((float4*)out)[node * 32 + lane] = res;
}

// ---------------- launch ----------------
extern "C" void kernel_launch(void* const* d_in, const int* in_sizes, int n_in,
                              void* d_out, int out_size)
{
    const float* x       = (const float*)d_in[0];
    const void*  ei      = d_in[1];
    const float* W       = (const float*)d_in[2];
    const float* att_src = (const float*)d_in[3];
    const float* att_dst = (const float*)d_in[4];
    const float* bias    = (const float*)d_in[5];
    const float* gamma   = (const float*)d_in[6];
    const float* beta    = (const float*)d_in[7];
    float*       out     = (float*)d_out;

    int n = in_sizes[0] / DD;     // 50000
    int E = in_sizes[1] / 2;      // 600000
    int nb = (n + 255) / 256;     // 196

    const int GEMM_SMEM = (128 * XS_STRIDE) * 4 + (128 * WP_STRIDE) * 8; // 202752B
    cudaFuncSetAttribute(gemm_kernel, cudaFuncAttributeMaxDynamicSharedMemorySize, GEMM_SMEM);

    detect_zero_kernel<<<nb, 256>>>((const int*)ei, E, n);
    gemm_kernel<<<(n + 127) / 128, 256, GEMM_SMEM>>>(x, W, att_src, att_dst, n);
    hist_kernel<<<(E + 255) / 256, 256>>>(ei, E);
    scan_local_kernel<<<nb, 256>>>(n);
    scan_fixup_kernel<<<nb, 256>>>(n, nb);
    scatter_kernel<<<(E + 255) / 256, 256>>>(ei, E);
    agg_ln_kernel<<<(n + 7) / 8, 256>>>(x, bias, gamma, beta, out, n);
}

// round 7
// speedup vs baseline: 1.1034x; 1.1034x over previous
#include <cuda_runtime.h>
#include <cuda_bf16.h>
#include <math.h>

#define NN_MAX 50000
#define EE_MAX 600000
#define DD 128
#define HH 4
#define CC 32
#define NEG_SLOPE 0.2f
#define LN_EPS 1e-5f
#define NB_MAX 256

// ---------------- device scratch ----------------
static __device__ float g_h[NN_MAX * DD];
static __device__ float g_asrc[NN_MAX * HH];
static __device__ float g_adst[NN_MAX * HH];
static __device__ int   g_deg[NN_MAX];
static __device__ int   g_rowoff[NN_MAX];
static __device__ int   g_cursor[NN_MAX];
static __device__ int   g_srclist[EE_MAX];
static __device__ int   g_bsum[NB_MAX];
static __device__ int   g_is64;
static __device__ int          g_bar_count;
static __device__ volatile int g_bar_gen;

// ---------------- f32x2 helpers ----------------
__device__ __forceinline__ unsigned long long pk2(float lo, float hi) {
    unsigned long long r;
    asm("mov.b64 %0, {%1, %2};" : "=l"(r) : "f"(lo), "f"(hi));
    return r;
}
__device__ __forceinline__ unsigned long long fma2(unsigned long long a,
                                                   unsigned long long b,
                                                   unsigned long long c) {
    unsigned long long d;
    asm("fma.rn.f32x2 %0, %1, %2, %3;" : "=l"(d) : "l"(a), "l"(b), "l"(c));
    return d;
}
__device__ __forceinline__ float2 upk2(unsigned long long v) {
    float lo, hi;
    asm("mov.b64 {%0, %1}, %2;" : "=f"(lo), "=f"(hi) : "l"(v));
    return make_float2(lo, hi);
}
__device__ __forceinline__ float lrelu(float v) {
    return (v > 0.f) ? v : v * NEG_SLOPE;
}

__device__ __forceinline__ int edge_src(const void* ei, int E, int e) {
    if (g_is64) return (int)((const long long*)ei)[e];
    return ((const int*)ei)[e];
}
__device__ __forceinline__ int edge_dst(const void* ei, int E, int e) {
    if (g_is64) return (int)((const long long*)ei)[E + e];
    return ((const int*)ei)[E + e];
}

// ---------------- software grid barrier (all blocks co-resident) --------
__device__ __forceinline__ void grid_barrier(int nblocks) {
    __syncthreads();
    if (threadIdx.x == 0) {
        int gen = g_bar_gen;
        __threadfence();
        if (atomicAdd(&g_bar_count, 1) == nblocks - 1) {
            g_bar_count = 0;
            __threadfence();
            g_bar_gen = gen + 1;
        } else {
            while (g_bar_gen == gen) { __nanosleep(64); }
        }
        __threadfence();
    }
    __syncthreads();
}

// ---------------- fused CSR-build (persistent, 1 kernel) ----------------
__global__ __launch_bounds__(256)
void csr_fused_kernel(const int* __restrict__ ei32, const void* __restrict__ ei,
                      int E, int n, int nblocks)
{
    int tid = threadIdx.x;
    int bid = blockIdx.x;
    int gthread = bid * 256 + tid;
    int gstride = nblocks * 256;

    __shared__ int wsum[8];
    __shared__ int s_base;

    // ---- Phase 0: zero degrees; block 0 detects dtype ----
    for (int i = gthread; i < n; i += gstride) g_deg[i] = 0;
    if (bid == 0) {
        int checks = 2 * E; if (checks > 4096) checks = 4096;
        int nz = 0;
        for (int j = tid; j < checks; j += 256)
            if (ei32[2 * j + 1] != 0) nz = 1;
        #pragma unroll
        for (int o = 16; o >= 1; o >>= 1)
            nz |= __shfl_xor_sync(0xffffffffu, nz, o);
        __shared__ int s_nz[8];
        if ((tid & 31) == 0) s_nz[tid >> 5] = nz;
        __syncthreads();
        if (tid == 0) {
            int a = 0;
            for (int w = 0; w < 8; w++) a |= s_nz[w];
            g_is64 = (a == 0) ? 1 : 0;
        }
    }
    grid_barrier(nblocks);

    // ---- Phase 1: histogram ----
    for (int e = gthread; e < E; e += gstride) {
        int d = edge_dst(ei, E, e);
        atomicAdd(&g_deg[d], 1);
    }
    grid_barrier(nblocks);

    // ---- Phase 2a: block-local exclusive scan (first nb blocks) ----
    int nb = (n + 255) / 256;
    if (bid < nb) {
        int i = bid * 256 + tid;
        int lane = tid & 31;
        int wid  = tid >> 5;
        int v = (i < n) ? g_deg[i] : 0;
        int inc = v;
        #pragma unroll
        for (int o = 1; o < 32; o <<= 1) {
            int t = __shfl_up_sync(0xffffffffu, inc, o);
            if (lane >= o) inc += t;
        }
        if (lane == 31) wsum[wid] = inc;
        __syncthreads();
        if (wid == 0) {
            int ws = (lane < 8) ? wsum[lane] : 0;
            #pragma unroll
            for (int o = 1; o < 8; o <<= 1) {
                int t = __shfl_up_sync(0xffffffffu, ws, o);
                if (lane >= o) ws += t;
            }
            if (lane < 8) wsum[lane] = ws;
        }
        __syncthreads();
        int warpbase = (wid == 0) ? 0 : wsum[wid - 1];
        int excl = warpbase + inc - v;
        if (i < n) g_rowoff[i] = excl;
        if (tid == 255) g_bsum[bid] = warpbase + inc;
    }
    grid_barrier(nblocks);

    // ---- Phase 2b: fixup (first nb blocks) ----
    if (bid < nb) {
        if (tid < 32) {
            int b = 0;
            for (int j = tid; j < bid; j += 32) b += g_bsum[j];
            #pragma unroll
            for (int o = 16; o >= 1; o >>= 1)
                b += __shfl_xor_sync(0xffffffffu, b, o);
            if (tid == 0) s_base = b;
        }
        __syncthreads();
        int i = bid * 256 + tid;
        if (i < n) {
            int r = g_rowoff[i] + s_base;
            g_rowoff[i] = r;
            g_cursor[i] = r;
        }
    }
    grid_barrier(nblocks);

    // ---- Phase 3: scatter edges into CSR ----
    for (int e = gthread; e < E; e += gstride) {
        int s = edge_src(ei, E, e);
        int d = edge_dst(ei, E, e);
        int pos = atomicAdd(&g_cursor[d], 1);
        g_srclist[pos] = s;
    }
}

// ---------------- fallback separate kernels (if grid too small) ---------
__global__ void detect_zero_kernel(const int* __restrict__ ei32, int E, int n)
{
    int i = blockIdx.x * 256 + threadIdx.x;
    if (i < n) g_deg[i] = 0;
    if (blockIdx.x == 0) {
        int checks = 2 * E; if (checks > 4096) checks = 4096;
        int nz = 0;
        for (int j = threadIdx.x; j < checks; j += 256)
            if (ei32[2 * j + 1] != 0) nz = 1;
        #pragma unroll
        for (int o = 16; o >= 1; o >>= 1)
            nz |= __shfl_xor_sync(0xffffffffu, nz, o);
        __shared__ int s_nz[8];
        if ((threadIdx.x & 31) == 0) s_nz[threadIdx.x >> 5] = nz;
        __syncthreads();
        if (threadIdx.x == 0) {
            int a = 0;
            for (int w = 0; w < 8; w++) a |= s_nz[w];
            g_is64 = (a == 0) ? 1 : 0;
        }
    }
}
__global__ void hist_kernel(const void* __restrict__ ei, int E)
{
    int e = blockIdx.x * 256 + threadIdx.x;
    if (e < E) atomicAdd(&g_deg[edge_dst(ei, E, e)], 1);
}
__global__ __launch_bounds__(256)
void scan_local_kernel(int n)
{
    int i = blockIdx.x * 256 + threadIdx.x;
    int lane = threadIdx.x & 31;
    int wid  = threadIdx.x >> 5;
    int v = (i < n) ? g_deg[i] : 0;
    int inc = v;
    #pragma unroll
    for (int o = 1; o < 32; o <<= 1) {
        int t = __shfl_up_sync(0xffffffffu, inc, o);
        if (lane >= o) inc += t;
    }
    __shared__ int wsum[8];
    if (lane == 31) wsum[wid] = inc;
    __syncthreads();
    if (wid == 0) {
        int ws = (lane < 8) ? wsum[lane] : 0;
        #pragma unroll
        for (int o = 1; o < 8; o <<= 1) {
            int t = __shfl_up_sync(0xffffffffu, ws, o);
            if (lane >= o) ws += t;
        }
        if (lane < 8) wsum[lane] = ws;
    }
    __syncthreads();
    int warpbase = (wid == 0) ? 0 : wsum[wid - 1];
    int excl = warpbase + inc - v;
    if (i < n) g_rowoff[i] = excl;
    if (threadIdx.x == 255) g_bsum[blockIdx.x] = warpbase + inc;
}
__global__ __launch_bounds__(256)
void scan_fixup_kernel(int n, int nb)
{
    __shared__ int s_base;
    if (threadIdx.x < 32) {
        int b = 0;
        for (int j = threadIdx.x; j < blockIdx.x; j += 32) b += g_bsum[j];
        #pragma unroll
        for (int o = 16; o >= 1; o >>= 1)
            b += __shfl_xor_sync(0xffffffffu, b, o);
        if (threadIdx.x == 0) s_base = b;
    }
    __syncthreads();
    int i = blockIdx.x * 256 + threadIdx.x;
    if (i < n) {
        int r = g_rowoff[i] + s_base;
        g_rowoff[i] = r;
        g_cursor[i] = r;
    }
}
__global__ void scatter_kernel(const void* __restrict__ ei, int E)
{
    int e = blockIdx.x * 256 + threadIdx.x;
    if (e < E) {
        int s = edge_src(ei, E, e);
        int d = edge_dst(ei, E, e);
        int pos = atomicAdd(&g_cursor[d], 1);
        g_srclist[pos] = s;
    }
}

// ---------------- Kernel 1: h = x @ W + fused attention logits ----------
// (R4 proven version — f32x2 FMA)
__global__ __launch_bounds__(256, 2)
void gemm_kernel(const float* __restrict__ x, const float* __restrict__ W,
                 const float* __restrict__ att_src, const float* __restrict__ att_dst,
                 int n)
{
    extern __shared__ float smem[];
    float* ws = smem;              // [128][128]
    float* xs = smem + 128 * 128;  // [64][128]

    int rowbase = blockIdx.x * 64;

    const float4* W4 = (const float4*)W;
    float4* ws4 = (float4*)ws;
    #pragma unroll
    for (int t = threadIdx.x; t < 4096; t += 256) ws4[t] = W4[t];

    float4* xs4 = (float4*)xs;
    const float4* x4in = (const float4*)x;
    #pragma unroll
    for (int t = threadIdx.x; t < 2048; t += 256) {
        int r = t >> 5, k4 = t & 31;
        int grow = rowbase + r;
        float4 v = make_float4(0.f, 0.f, 0.f, 0.f);
        if (grow < n) v = x4in[grow * 32 + k4];
        xs4[r * 32 + k4] = v;
    }
    __syncthreads();

    int rg = threadIdx.x >> 5;
    int cg = threadIdx.x & 31;

    unsigned long long acc0[8], acc1[8];
    #pragma unroll
    for (int i = 0; i < 8; i++) { acc0[i] = 0ull; acc1[i] = 0ull; }

    const float* xrow = xs + rg * 8 * 128;
    const ulonglong2* ws2 = (const ulonglong2*)ws;

    #pragma unroll 4
    for (int k = 0; k < 128; k++) {
        ulonglong2 wv = ws2[k * 32 + cg];
        #pragma unroll
        for (int i = 0; i < 8; i++) {
            float xv = xrow[i * 128 + k];
            unsigned long long xx = pk2(xv, xv);
            acc0[i] = fma2(xx, wv.x, acc0[i]);
            acc1[i] = fma2(xx, wv.y, acc1[i]);
        }
    }

    float4 as4 = ((const float4*)att_src)[cg];
    float4 ad4 = ((const float4*)att_dst)[cg];
    float4* h4 = (float4*)g_h;
    int head = cg >> 3;

    #pragma unroll
    for (int i = 0; i < 8; i++) {
        float2 a = upk2(acc0[i]);
        float2 b = upk2(acc1[i]);
        float4 hv = make_float4(a.x, a.y, b.x, b.y);
        float ps = hv.x * as4.x + hv.y * as4.y + hv.z * as4.z + hv.w * as4.w;
        float pd = hv.x * ad4.x + hv.y * ad4.y + hv.z * ad4.z + hv.w * ad4.w;
        #pragma unroll
        for (int o = 4; o >= 1; o >>= 1) {
            ps += __shfl_xor_sync(0xffffffffu, ps, o);
            pd += __shfl_xor_sync(0xffffffffu, pd, o);
        }
        int grow = rowbase + rg * 8 + i;
        if (grow < n) {
            h4[grow * 32 + cg] = hv;
            if ((cg & 7) == 0) {
                g_asrc[grow * HH + head] = ps;
                g_adst[grow * HH + head] = pd;
            }
        }
    }
}

// ---------------- Kernel 5: fused softmax-agg + GELU + LN + residual ----
// R3 structure, main loop 4x-unrolled (4 independent FMA chains).
__global__ __launch_bounds__(256)
void agg_ln_kernel(const float* __restrict__ x,
                   const float* __restrict__ bias,
                   const float* __restrict__ gamma,
                   const float* __restrict__ beta,
                   float* __restrict__ out, int n)
{
    int node = blockIdx.x * 8 + (threadIdx.x >> 5);
    if (node >= n) return;
    int lane = threadIdx.x & 31;
    int hd8 = lane >> 3;
    int hd4 = lane & 3;
    int esub = lane >> 2;

    int beg = g_rowoff[node];
    int cnt = g_deg[node];

    float aself = g_asrc[node * HH + hd4];
    float adst4 = g_adst[node * HH + hd4];

    // Phase A: per-head max of a_src over {self} U neighbors
    float mx = aself;
    for (int k0 = 0; k0 < cnt; k0 += 8) {
        int k = k0 + esub;
        float v = -1e30f;
        if (k < cnt) {
            int s = g_srclist[beg + k];
            v = g_asrc[s * HH + hd4];
        }
        mx = fmaxf(mx, v);
    }
    mx = fmaxf(mx, __shfl_xor_sync(0xffffffffu, mx, 4));
    mx = fmaxf(mx, __shfl_xor_sync(0xffffffffu, mx, 8));
    mx = fmaxf(mx, __shfl_xor_sync(0xffffffffu, mx, 16));

    float mxh    = __shfl_sync(0xffffffffu, mx, hd8);
    float adst   = __shfl_sync(0xffffffffu, adst4, hd8);
    float aselfh = __shfl_sync(0xffffffffu, aself, hd8);
    float M = lrelu(mxh + adst);

    // Phase B: weighted aggregation, 4 independent chains
    const float4* h4 = (const float4*)g_h;
    float p0 = __expf(lrelu(aselfh + adst) - M);
    float4 hv = h4[node * 32 + lane];
    float4 accA = make_float4(p0 * hv.x, p0 * hv.y, p0 * hv.z, p0 * hv.w);
    float4 accB = make_float4(0.f, 0.f, 0.f, 0.f);
    float4 accC = make_float4(0.f, 0.f, 0.f, 0.f);
    float4 accD = make_float4(0.f, 0.f, 0.f, 0.f);
    float dA = p0, dB = 0.f, dC = 0.f, dD = 0.f;

    int k = 0;
    for (; k + 4 <= cnt; k += 4) {
        int sa = g_srclist[beg + k];
        int sb = g_srclist[beg + k + 1];
        int sc = g_srclist[beg + k + 2];
        int sd = g_srclist[beg + k + 3];
        float ea = g_asrc[sa * HH + hd8];
        float eb = g_asrc[sb * HH + hd8];
        float ec = g_asrc[sc * HH + hd8];
        float ed = g_asrc[sd * HH + hd8];
        float4 ha = h4[sa * 32 + lane];
        float4 hb = h4[sb * 32 + lane];
        float4 hc = h4[sc * 32 + lane];
        float4 hd = h4[sd * 32 + lane];
        float pa = __expf(lrelu(ea + adst) - M);
        float pb = __expf(lrelu(eb + adst) - M);
        float pc = __expf(lrelu(ec + adst) - M);
        float pd = __expf(lrelu(ed + adst) - M);
        dA += pa; dB += pb; dC += pc; dD += pd;
        accA.x = fmaf(pa, ha.x, accA.x); accA.y = fmaf(pa, ha.y, accA.y);
        accA.z = fmaf(pa, ha.z, accA.z); accA.w = fmaf(pa, ha.w, accA.w);
        accB.x = fmaf(pb, hb.x, accB.x); accB.y = fmaf(pb, hb.y, accB.y);
        accB.z = fmaf(pb, hb.z, accB.z); accB.w = fmaf(pb, hb.w, accB.w);
        accC.x = fmaf(pc, hc.x, accC.x); accC.y = fmaf(pc, hc.y, accC.y);
        accC.z = fmaf(pc, hc.z, accC.z); accC.w = fmaf(pc, hc.w, accC.w);
        accD.x = fmaf(pd, hd.x, accD.x); accD.y = fmaf(pd, hd.y, accD.y);
        accD.z = fmaf(pd, hd.z, accD.z); accD.w = fmaf(pd, hd.w, accD.w);
    }
    for (; k < cnt; k++) {
        int sa = g_srclist[beg + k];
        float ea = g_asrc[sa * HH + hd8];
        float4 ha = h4[sa * 32 + lane];
        float pa = __expf(lrelu(ea + adst) - M);
        dA += pa;
        accA.x = fmaf(pa, ha.x, accA.x); accA.y = fmaf(pa, ha.y, accA.y);
        accA.z = fmaf(pa, ha.z, accA.z); accA.w = fmaf(pa, ha.w, accA.w);
    }

    float denom = (dA + dB) + (dC + dD);
    float inv = 1.0f / denom;
    float4 bi = ((const float4*)bias)[lane];
    float4 sum = make_float4((accA.x + accB.x) + (accC.x + accD.x),
                             (accA.y + accB.y) + (accC.y + accD.y),
                             (accA.z + accB.z) + (accC.z + accD.z),
                             (accA.w + accB.w) + (accC.w + accD.w));
    float4 o = make_float4(fmaf(sum.x, inv, bi.x), fmaf(sum.y, inv, bi.y),
                           fmaf(sum.z, inv, bi.z), fmaf(sum.w, inv, bi.w));

    const float RS2 = 0.70710678118654752f;
    float4 f;
    f.x = 0.5f * o.x * (1.0f + erff(o.x * RS2));
    f.y = 0.5f * o.y * (1.0f + erff(o.y * RS2));
    f.z = 0.5f * o.z * (1.0f + erff(o.z * RS2));
    f.w = 0.5f * o.w * (1.0f + erff(o.w * RS2));

    float s1 = f.x + f.y + f.z + f.w;
    float s2 = f.x * f.x + f.y * f.y + f.z * f.z + f.w * f.w;
    #pragma unroll
    for (int off = 16; off >= 1; off >>= 1) {
        s1 += __shfl_xor_sync(0xffffffffu, s1, off);
        s2 += __shfl_xor_sync(0xffffffffu, s2, off);
    }
    float mu  = s1 * (1.0f / 128.0f);
    float var = s2 * (1.0f / 128.0f) - mu * mu;
    float r = rsqrtf(var + LN_EPS);

    float4 gm = ((const float4*)gamma)[lane];
    float4 bt = ((const float4*)beta)[lane];
    float4 xv = ((const float4*)x)[node * 32 + lane];
    float4 res;
    res.x = (f.x - mu) * r * gm.x + bt.x + xv.x;
    res.y = (f.y - mu) * r * gm.y + bt.y + xv.y;
    res.z = (f.z - mu) * r * gm.z + bt.z + xv.z;
    res.w = (f.w - mu) * r * gm.w + bt.w + xv.w;
    ((float4*)out)[node * 32 + lane] = res;
}

// ---------------- launch ----------------
extern "C" void kernel_launch(void* const* d_in, const int* in_sizes, int n_in,
                              void* d_out, int out_size)
{
    const float* x       = (const float*)d_in[0];
    const void*  ei      = d_in[1];
    const float* W       = (const float*)d_in[2];
    const float* att_src = (const float*)d_in[3];
    const float* att_dst = (const float*)d_in[4];
    const float* bias    = (const float*)d_in[5];
    const float* gamma   = (const float*)d_in[6];
    const float* beta    = (const float*)d_in[7];
    float*       out     = (float*)d_out;

    int n = in_sizes[0] / DD;     // 50000
    int E = in_sizes[1] / 2;      // 600000
    int nb = (n + 255) / 256;     // 196

    const int GEMM_SMEM = (128 * 128 + 64 * 128) * 4;  // 96KB
    cudaFuncSetAttribute(gemm_kernel, cudaFuncAttributeMaxDynamicSharedMemorySize, GEMM_SMEM);

    // co-resident grid size for the fused CSR kernel
    int dev = 0; cudaGetDevice(&dev);
    int sms = 0; cudaDeviceGetAttribute(&sms, cudaDevAttrMultiProcessorCount, dev);
    int maxb = 0;
    cudaOccupancyMaxActiveBlocksPerMultiprocessor(&maxb, csr_fused_kernel, 256, 0);
    int nblocks = sms * maxb;
    if (nblocks > 1184) nblocks = 1184;

    gemm_kernel<<<(n + 63) / 64, 256, GEMM_SMEM>>>(x, W, att_src, att_dst, n);

    if (nblocks >= nb) {
        csr_fused_kernel<<<nblocks, 256>>>((const int*)ei, ei, E, n, nblocks);
    } else {
        detect_zero_kernel<<<nb, 256>>>((const int*)ei, E, n);
        hist_kernel<<<(E + 255) / 256, 256>>>(ei, E);
        scan_local_kernel<<<nb, 256>>>(n);
        scan_fixup_kernel<<<nb, 256>>>(n, nb);
        scatter_kernel<<<(E + 255) / 256, 256>>>(ei, E);
    }
    agg_ln_kernel<<<(n + 7) / 8, 256>>>(x, bias, gamma, beta, out, n);
}